// round 6
// baseline (speedup 1.0000x reference)
#include <cuda_runtime.h>
#include <cstdint>

#define NN 50000
#define EE 800000
#define FIN 128
#define HH 4
#define FO 64
#define NOUT 256   // HH*FO

// ---- static scratch ----
__device__ float g_z[NN * HH * FIN];  // aggregated features in input space [N,4,128]
__device__ float g_el2[NN * HH];
__device__ float g_er2[NN * HH];
__device__ float g_wc[HH * FIN];
__device__ int   g_counts[NN];
__device__ int   g_offsets[NN + 1];
__device__ int   g_cursor[NN];
__device__ int   g_csr_src[EE];
__device__ int   g_chunksum[64];

// ---- packed f32x2 helpers (kept for agg; known-neutral but working) ----
typedef unsigned long long u64t;
__device__ __forceinline__ u64t pack2(float lo, float hi) {
    u64t r;
    asm("mov.b64 %0, {%1, %2};" : "=l"(r) : "f"(lo), "f"(hi));
    return r;
}
__device__ __forceinline__ void unpack2(u64t v, float& lo, float& hi) {
    asm("mov.b64 {%0, %1}, %2;" : "=f"(lo), "=f"(hi) : "l"(v));
}
__device__ __forceinline__ void ffma2(u64t& d, u64t a, u64t b) {
    asm("fma.rn.f32x2 %0, %1, %2, %0;" : "+l"(d) : "l"(a), "l"(b));
}
__device__ __forceinline__ u64t fmul2(u64t a, u64t b) {
    u64t r;
    asm("mul.rn.f32x2 %0, %1, %2;" : "=l"(r) : "l"(a), "l"(b));
    return r;
}

// ---- tf32 helpers ----
__device__ __forceinline__ void tf32_split(float x, uint32_t& hi, uint32_t& lo) {
    asm("cvt.rna.tf32.f32 %0, %1;" : "=r"(hi) : "f"(x));
    float hif = __uint_as_float(hi);
    float lof = x - hif;
    asm("cvt.rna.tf32.f32 %0, %1;" : "=r"(lo) : "f"(lof));
}
__device__ __forceinline__ void mma_tf32(float& d0, float& d1, float& d2, float& d3,
                                         uint32_t a0, uint32_t a1, uint32_t a2, uint32_t a3,
                                         uint32_t b0, uint32_t b1) {
    asm("mma.sync.aligned.m16n8k8.row.col.f32.tf32.tf32.f32 "
        "{%0,%1,%2,%3}, {%4,%5,%6,%7}, {%8,%9}, {%0,%1,%2,%3};"
        : "+f"(d0), "+f"(d1), "+f"(d2), "+f"(d3)
        : "r"(a0), "r"(a1), "r"(a2), "r"(a3), "r"(b0), "r"(b1));
}

// ---------------- prep: wc + zero counts ----------------
__global__ void k_prep(const float* __restrict__ al, const float* __restrict__ ar,
                       const float* __restrict__ al1, const float* __restrict__ ar1) {
    int i = blockIdx.x * blockDim.x + threadIdx.x;
    if (i < HH * FIN) g_wc[i] = al[i] * ar[i] - 2.0f * al1[i] * ar1[i];
    if (i < NN) g_counts[i] = 0;
}

// ---------------- per-node el2/er2 ----------------
__global__ void k_node(const float* __restrict__ feat,
                       const float* __restrict__ al1, const float* __restrict__ ar1) {
    int warp = (blockIdx.x * blockDim.x + threadIdx.x) >> 5;
    int lane = threadIdx.x & 31;
    if (warp >= NN) return;
    float4 f = *(const float4*)(feat + warp * FIN + lane * 4);
    float q0 = f.x * f.x, q1 = f.y * f.y, q2 = f.z * f.z, q3 = f.w * f.w;
    float pl[4], pr[4];
#pragma unroll
    for (int h = 0; h < 4; h++) {
        float4 a = *(const float4*)(al1 + h * FIN + lane * 4);
        float4 b = *(const float4*)(ar1 + h * FIN + lane * 4);
        pl[h] = q0 * a.x * a.x + q1 * a.y * a.y + q2 * a.z * a.z + q3 * a.w * a.w;
        pr[h] = q0 * b.x * b.x + q1 * b.y * b.y + q2 * b.z * b.z + q3 * b.w * b.w;
    }
#pragma unroll
    for (int off = 16; off; off >>= 1) {
#pragma unroll
        for (int h = 0; h < 4; h++) {
            pl[h] += __shfl_xor_sync(0xffffffffu, pl[h], off);
            pr[h] += __shfl_xor_sync(0xffffffffu, pr[h], off);
        }
    }
    if (lane == 0) {
        *(float4*)(g_el2 + warp * 4) = make_float4(pl[0], pl[1], pl[2], pl[3]);
        *(float4*)(g_er2 + warp * 4) = make_float4(pr[0], pr[1], pr[2], pr[3]);
    }
}

// ---------------- CSR build ----------------
__global__ void k_hist(const int* __restrict__ dst) {
    int e4 = (blockIdx.x * blockDim.x + threadIdx.x) * 4;
    if (e4 < EE) {
        int4 d4 = *(const int4*)(dst + e4);
        atomicAdd(&g_counts[d4.x], 1);
        atomicAdd(&g_counts[d4.y], 1);
        atomicAdd(&g_counts[d4.z], 1);
        atomicAdd(&g_counts[d4.w], 1);
    }
}

__global__ void k_scan1() {
    __shared__ int wsum[32];
    int tid = threadIdx.x;
    int t = blockIdx.x * 1024 + tid;
    int lane = tid & 31, wid = tid >> 5;
    int x = (t < NN) ? g_counts[t] : 0;
#pragma unroll
    for (int off = 1; off < 32; off <<= 1) {
        int y = __shfl_up_sync(0xffffffffu, x, off);
        if (lane >= off) x += y;
    }
    if (lane == 31) wsum[wid] = x;
    __syncthreads();
    if (wid == 0) {
        int ws = wsum[lane];
#pragma unroll
        for (int off = 1; off < 32; off <<= 1) {
            int y = __shfl_up_sync(0xffffffffu, ws, off);
            if (lane >= off) ws += y;
        }
        wsum[lane] = ws;
    }
    __syncthreads();
    if (wid > 0) x += wsum[wid - 1];
    if (t < NN) g_offsets[t + 1] = x;
    if (tid == 1023) g_chunksum[blockIdx.x] = x;
}
__global__ void k_scan2(int nch) {
    if (threadIdx.x == 0 && blockIdx.x == 0) {
        int run = 0;
        for (int i = 0; i < nch; i++) { int t = g_chunksum[i]; g_chunksum[i] = run; run += t; }
    }
}
__global__ void k_scan3() {
    int tid = threadIdx.x;
    int t = blockIdx.x * 1024 + tid;
    if (t < NN) {
        int inc = g_offsets[t + 1] + g_chunksum[blockIdx.x];
        g_offsets[t + 1] = inc;
        g_cursor[t] = inc - g_counts[t];
    }
    if (t == 0) g_offsets[0] = 0;
}
__global__ void k_scatter(const int* __restrict__ src, const int* __restrict__ dst) {
    int e4 = (blockIdx.x * blockDim.x + threadIdx.x) * 4;
    if (e4 < EE) {
        int4 s4 = *(const int4*)(src + e4);
        int4 d4 = *(const int4*)(dst + e4);
        int p0 = atomicAdd(&g_cursor[d4.x], 1); g_csr_src[p0] = s4.x;
        int p1 = atomicAdd(&g_cursor[d4.y], 1); g_csr_src[p1] = s4.y;
        int p2 = atomicAdd(&g_cursor[d4.z], 1); g_csr_src[p2] = s4.z;
        int p3 = atomicAdd(&g_cursor[d4.w], 1); g_csr_src[p3] = s4.w;
    }
}

// ---------------- fused score + online-softmax + input-space agg ----------------
__global__ void __launch_bounds__(256)
k_agg(const float* __restrict__ feat) {
    int warp = (blockIdx.x * blockDim.x + threadIdx.x) >> 5;
    int lane = threadIdx.x & 31;
    if (warp >= NN) return;
    const int n = warp;
    const int start = g_offsets[n];
    const int end = g_offsets[n + 1];
    const int hsel = lane & 3;
    float* zp = g_z + (size_t)n * (HH * FIN);

    if (start == end) {  // z = 0 -> out = bias
        float4 zz = make_float4(0.f, 0.f, 0.f, 0.f);
#pragma unroll
        for (int h = 0; h < 4; h++) *(float4*)(zp + h * FIN + lane * 4) = zz;
        return;
    }

    float4 fd = *(const float4*)(feat + n * FIN + lane * 4);
    float4 c0 = *(const float4*)(g_wc + 0 * FIN + lane * 4);
    float4 c1 = *(const float4*)(g_wc + 1 * FIN + lane * 4);
    float4 c2 = *(const float4*)(g_wc + 2 * FIN + lane * 4);
    float4 c3 = *(const float4*)(g_wc + 3 * FIN + lane * 4);
    c0.x *= fd.x; c0.y *= fd.y; c0.z *= fd.z; c0.w *= fd.w;
    c1.x *= fd.x; c1.y *= fd.y; c1.z *= fd.z; c1.w *= fd.w;
    c2.x *= fd.x; c2.y *= fd.y; c2.z *= fd.z; c2.w *= fd.w;
    c3.x *= fd.x; c3.y *= fd.y; c3.z *= fd.z; c3.w *= fd.w;
    float er_s = __ldg(g_er2 + n * 4 + hsel);

    float m = -3.0e38f, s = 0.f;
    u64t z0a = 0, z0b = 0, z1a = 0, z1b = 0;
    u64t z2a = 0, z2b = 0, z3a = 0, z3b = 0;

    for (int idx = start; idx < end; ++idx) {
        int src = __ldg(g_csr_src + idx);
        float4 fs = *(const float4*)(feat + src * FIN + lane * 4);
        float el_s = __ldg(g_el2 + src * 4 + hsel);

        float p0 = fs.x * c0.x + fs.y * c0.y + fs.z * c0.z + fs.w * c0.w;
        float p1 = fs.x * c1.x + fs.y * c1.y + fs.z * c1.z + fs.w * c1.w;
        float p2 = fs.x * c2.x + fs.y * c2.y + fs.z * c2.z + fs.w * c2.w;
        float p3 = fs.x * c3.x + fs.y * c3.y + fs.z * c3.z + fs.w * c3.w;

        float u01 = (lane & 1) ? p1 : p0;
        float t01 = (lane & 1) ? p0 : p1;
        u01 += __shfl_xor_sync(0xffffffffu, t01, 1);
        float u23 = (lane & 1) ? p3 : p2;
        float t23 = (lane & 1) ? p2 : p3;
        u23 += __shfl_xor_sync(0xffffffffu, t23, 1);
        float v = (lane & 2) ? u23 : u01;
        float t = (lane & 2) ? u01 : u23;
        v += __shfl_xor_sync(0xffffffffu, t, 2);
        v += __shfl_xor_sync(0xffffffffu, v, 4);
        v += __shfl_xor_sync(0xffffffffu, v, 8);
        v += __shfl_xor_sync(0xffffffffu, v, 16);

        float e = v + el_s + er_s;

        float sc = 1.f;
        if (e > m) { sc = __expf(m - e); m = e; }
        float w = __expf(e - m);
        s = s * sc + w;

        float w0 = __shfl_sync(0xffffffffu, w, 0);
        float w1 = __shfl_sync(0xffffffffu, w, 1);
        float w2 = __shfl_sync(0xffffffffu, w, 2);
        float w3 = __shfl_sync(0xffffffffu, w, 3);

        if (__any_sync(0xffffffffu, sc != 1.0f)) {
            float s0 = __shfl_sync(0xffffffffu, sc, 0);
            float s1 = __shfl_sync(0xffffffffu, sc, 1);
            float s2 = __shfl_sync(0xffffffffu, sc, 2);
            float s3 = __shfl_sync(0xffffffffu, sc, 3);
            u64t sd0 = pack2(s0, s0), sd1 = pack2(s1, s1);
            u64t sd2 = pack2(s2, s2), sd3 = pack2(s3, s3);
            z0a = fmul2(z0a, sd0); z0b = fmul2(z0b, sd0);
            z1a = fmul2(z1a, sd1); z1b = fmul2(z1b, sd1);
            z2a = fmul2(z2a, sd2); z2b = fmul2(z2b, sd2);
            z3a = fmul2(z3a, sd3); z3b = fmul2(z3b, sd3);
        }
        u64t fsa = pack2(fs.x, fs.y), fsb = pack2(fs.z, fs.w);
        u64t wd0 = pack2(w0, w0), wd1 = pack2(w1, w1);
        u64t wd2 = pack2(w2, w2), wd3 = pack2(w3, w3);
        ffma2(z0a, wd0, fsa); ffma2(z0b, wd0, fsb);
        ffma2(z1a, wd1, fsa); ffma2(z1b, wd1, fsb);
        ffma2(z2a, wd2, fsa); ffma2(z2b, wd2, fsb);
        ffma2(z3a, wd3, fsa); ffma2(z3b, wd3, fsb);
    }

    float rinv = 1.f / s;
    float r0 = __shfl_sync(0xffffffffu, rinv, 0);
    float r1 = __shfl_sync(0xffffffffu, rinv, 1);
    float r2 = __shfl_sync(0xffffffffu, rinv, 2);
    float r3 = __shfl_sync(0xffffffffu, rinv, 3);

    float4 o;
    unpack2(z0a, o.x, o.y); unpack2(z0b, o.z, o.w);
    *(float4*)(zp + 0 * FIN + lane * 4) = make_float4(o.x * r0, o.y * r0, o.z * r0, o.w * r0);
    unpack2(z1a, o.x, o.y); unpack2(z1b, o.z, o.w);
    *(float4*)(zp + 1 * FIN + lane * 4) = make_float4(o.x * r1, o.y * r1, o.z * r1, o.w * r1);
    unpack2(z2a, o.x, o.y); unpack2(z2b, o.z, o.w);
    *(float4*)(zp + 2 * FIN + lane * 4) = make_float4(o.x * r2, o.y * r2, o.z * r2, o.w * r2);
    unpack2(z3a, o.x, o.y); unpack2(z3b, o.z, o.w);
    *(float4*)(zp + 3 * FIN + lane * 4) = make_float4(o.x * r3, o.y * r3, o.z * r3, o.w * r3);
}

// ---------------- tensor-core split-tf32 GEMM: out^T = W_h @ z_h^T ----------------
// grid (HH, 391), block 128 (4 warps). Warp w owns output channels w*16..w*16+15.
// Block covers 128 nodes (16 n-frags of 8). 3-pass tf32: hi*hi + hi*lo + lo*hi.
__global__ void __launch_bounds__(128)
k_tc(const float* __restrict__ W, const float* __restrict__ bias,
     float* __restrict__ out) {
    const int h = blockIdx.x;
    const int nBase = blockIdx.y * 128;
    const int tid = threadIdx.x;
    const int w = tid >> 5;
    const int lane = tid & 31;
    const int g = lane >> 2;       // 0..7
    const int t4 = lane & 3;       // 0..3

    float acc[16][4];
#pragma unroll
    for (int i = 0; i < 16; i++)
#pragma unroll
        for (int j = 0; j < 4; j++) acc[i][j] = 0.f;

    const float* Wh = W + (size_t)(h * FO) * FIN;

#pragma unroll 1
    for (int kf = 0; kf < 16; kf++) {
        const int k0 = kf * 8;
        // A frag: W rows (channels) w*16+g, w*16+g+8 ; cols k0+t4, k0+t4+4
        float a0f = __ldg(Wh + (w * 16 + g) * FIN + k0 + t4);
        float a1f = __ldg(Wh + (w * 16 + g + 8) * FIN + k0 + t4);
        float a2f = __ldg(Wh + (w * 16 + g) * FIN + k0 + t4 + 4);
        float a3f = __ldg(Wh + (w * 16 + g + 8) * FIN + k0 + t4 + 4);
        uint32_t ah0, al0, ah1, al1, ah2, al2, ah3, al3;
        tf32_split(a0f, ah0, al0);
        tf32_split(a1f, ah1, al1);
        tf32_split(a2f, ah2, al2);
        tf32_split(a3f, ah3, al3);

#pragma unroll
        for (int nf = 0; nf < 16; nf++) {
            int node = nBase + nf * 8 + g;
            float b0f = 0.f, b1f = 0.f;
            if (node < NN) {
                const float* zr = g_z + (size_t)node * (HH * FIN) + h * FIN + k0 + t4;
                b0f = __ldg(zr);
                b1f = __ldg(zr + 4);
            }
            uint32_t bh0, bl0, bh1, bl1;
            tf32_split(b0f, bh0, bl0);
            tf32_split(b1f, bh1, bl1);
            mma_tf32(acc[nf][0], acc[nf][1], acc[nf][2], acc[nf][3],
                     ah0, ah1, ah2, ah3, bh0, bh1);
            mma_tf32(acc[nf][0], acc[nf][1], acc[nf][2], acc[nf][3],
                     ah0, ah1, ah2, ah3, bl0, bl1);
            mma_tf32(acc[nf][0], acc[nf][1], acc[nf][2], acc[nf][3],
                     al0, al1, al2, al3, bh0, bh1);
        }
    }

    // store: acc[nf] frag D[m16][n8]: c0 = D[g][2*t4] (channel w*16+g, node nf*8+2*t4)
    float bg  = __ldg(bias + h * FO + w * 16 + g);
    float bg8 = __ldg(bias + h * FO + w * 16 + g + 8);
    int ch  = h * FO + w * 16 + g;
    int ch8 = ch + 8;
#pragma unroll
    for (int nf = 0; nf < 16; nf++) {
        int n0 = nBase + nf * 8 + 2 * t4;
        int n1 = n0 + 1;
        if (n0 < NN) {
            out[(size_t)n0 * NOUT + ch]  = acc[nf][0] + bg;
            out[(size_t)n0 * NOUT + ch8] = acc[nf][2] + bg8;
        }
        if (n1 < NN) {
            out[(size_t)n1 * NOUT + ch]  = acc[nf][1] + bg;
            out[(size_t)n1 * NOUT + ch8] = acc[nf][3] + bg8;
        }
    }
}

// ---------------- launch ----------------
extern "C" void kernel_launch(void* const* d_in, const int* in_sizes, int n_in,
                              void* d_out, int out_size) {
    const float* feat  = (const float*)d_in[0];
    const int*   src   = (const int*)d_in[1];
    const int*   dst   = (const int*)d_in[2];
    const float* fc_w  = (const float*)d_in[3];
    const float* al    = (const float*)d_in[4];
    const float* ar    = (const float*)d_in[5];
    const float* al1   = (const float*)d_in[6];
    const float* ar1   = (const float*)d_in[7];
    const float* bias  = (const float*)d_in[8];
    float* out = (float*)d_out;

    const int nch = (NN + 1023) / 1024;  // 49

    k_prep<<<(NN + 255) / 256, 256>>>(al, ar, al1, ar1);
    k_hist<<<(EE / 4 + 255) / 256, 256>>>(dst);
    k_node<<<(NN * 32 + 255) / 256, 256>>>(feat, al1, ar1);
    k_scan1<<<nch, 1024>>>();
    k_scan2<<<1, 32>>>(nch);
    k_scan3<<<nch, 1024>>>();
    k_scatter<<<(EE / 4 + 255) / 256, 256>>>(src, dst);
    k_agg<<<(NN * 32 + 255) / 256, 256>>>(feat);
    k_tc<<<dim3(HH, (NN + 127) / 128), 128>>>(fc_w, bias, out);
}

// round 7
// speedup vs baseline: 1.2423x; 1.2423x over previous
#include <cuda_runtime.h>
#include <cstdint>

#define NN 50000
#define NR 50048      // 391 * 128
#define EE 800000
#define FIN 128
#define HH 4
#define FO 64
#define NOUT 256

// ---- static scratch ----
__device__ float g_zh[(size_t)NR * 512];  // z tf32-hi as float [n][h][128]
__device__ float g_zl[(size_t)NR * 512];  // z tf32-lo
__device__ float g_wsh[NOUT * FIN];       // W tf32-hi
__device__ float g_wsl[NOUT * FIN];       // W tf32-lo
__device__ float g_el2[NN * HH];
__device__ float g_er2[NN * HH];
__device__ float g_wc[HH * FIN];
__device__ int   g_counts[NN];
__device__ int   g_offsets[NN + 1];
__device__ int   g_cursor[NN];
__device__ int   g_csr_src[EE];
__device__ int   g_chunksum[64];

// ---- tf32 helpers ----
__device__ __forceinline__ float tf32_rna(float x) {
    uint32_t r;
    asm("cvt.rna.tf32.f32 %0, %1;" : "=r"(r) : "f"(x));
    return __uint_as_float(r);
}
__device__ __forceinline__ void mma_tf32(float& d0, float& d1, float& d2, float& d3,
                                         uint32_t a0, uint32_t a1, uint32_t a2, uint32_t a3,
                                         uint32_t b0, uint32_t b1) {
    asm("mma.sync.aligned.m16n8k8.row.col.f32.tf32.tf32.f32 "
        "{%0,%1,%2,%3}, {%4,%5,%6,%7}, {%8,%9}, {%0,%1,%2,%3};"
        : "+f"(d0), "+f"(d1), "+f"(d2), "+f"(d3)
        : "r"(a0), "r"(a1), "r"(a2), "r"(a3), "r"(b0), "r"(b1));
}

// ---------------- prep: wc + W split + zero counts ----------------
__global__ void k_prep(const float* __restrict__ al, const float* __restrict__ ar,
                       const float* __restrict__ al1, const float* __restrict__ ar1,
                       const float* __restrict__ W) {
    int i = blockIdx.x * blockDim.x + threadIdx.x;
    if (i < HH * FIN) g_wc[i] = al[i] * ar[i] - 2.0f * al1[i] * ar1[i];
    if (i < NOUT * FIN) {
        float w = W[i];
        float hi = tf32_rna(w);
        g_wsh[i] = hi;
        g_wsl[i] = tf32_rna(w - hi);
    }
    if (i < NN) g_counts[i] = 0;
}

// ---------------- per-node el2/er2 ----------------
__global__ void k_node(const float* __restrict__ feat,
                       const float* __restrict__ al1, const float* __restrict__ ar1) {
    int warp = (blockIdx.x * blockDim.x + threadIdx.x) >> 5;
    int lane = threadIdx.x & 31;
    if (warp >= NN) return;
    float4 f = *(const float4*)(feat + warp * FIN + lane * 4);
    float q0 = f.x * f.x, q1 = f.y * f.y, q2 = f.z * f.z, q3 = f.w * f.w;
    float pl[4], pr[4];
#pragma unroll
    for (int h = 0; h < 4; h++) {
        float4 a = *(const float4*)(al1 + h * FIN + lane * 4);
        float4 b = *(const float4*)(ar1 + h * FIN + lane * 4);
        pl[h] = q0 * a.x * a.x + q1 * a.y * a.y + q2 * a.z * a.z + q3 * a.w * a.w;
        pr[h] = q0 * b.x * b.x + q1 * b.y * b.y + q2 * b.z * b.z + q3 * b.w * b.w;
    }
#pragma unroll
    for (int off = 16; off; off >>= 1) {
#pragma unroll
        for (int h = 0; h < 4; h++) {
            pl[h] += __shfl_xor_sync(0xffffffffu, pl[h], off);
            pr[h] += __shfl_xor_sync(0xffffffffu, pr[h], off);
        }
    }
    if (lane == 0) {
        *(float4*)(g_el2 + warp * 4) = make_float4(pl[0], pl[1], pl[2], pl[3]);
        *(float4*)(g_er2 + warp * 4) = make_float4(pr[0], pr[1], pr[2], pr[3]);
    }
}

// ---------------- CSR build ----------------
__global__ void k_hist(const int* __restrict__ dst) {
    int e4 = (blockIdx.x * blockDim.x + threadIdx.x) * 4;
    if (e4 < EE) {
        int4 d4 = *(const int4*)(dst + e4);
        atomicAdd(&g_counts[d4.x], 1);
        atomicAdd(&g_counts[d4.y], 1);
        atomicAdd(&g_counts[d4.z], 1);
        atomicAdd(&g_counts[d4.w], 1);
    }
}

__global__ void k_scan1() {
    __shared__ int wsum[32];
    int tid = threadIdx.x;
    int t = blockIdx.x * 1024 + tid;
    int lane = tid & 31, wid = tid >> 5;
    int x = (t < NN) ? g_counts[t] : 0;
#pragma unroll
    for (int off = 1; off < 32; off <<= 1) {
        int y = __shfl_up_sync(0xffffffffu, x, off);
        if (lane >= off) x += y;
    }
    if (lane == 31) wsum[wid] = x;
    __syncthreads();
    if (wid == 0) {
        int ws = wsum[lane];
#pragma unroll
        for (int off = 1; off < 32; off <<= 1) {
            int y = __shfl_up_sync(0xffffffffu, ws, off);
            if (lane >= off) ws += y;
        }
        wsum[lane] = ws;
    }
    __syncthreads();
    if (wid > 0) x += wsum[wid - 1];
    if (t < NN) g_offsets[t + 1] = x;
    if (tid == 1023) g_chunksum[blockIdx.x] = x;
}
__global__ void k_scan2(int nch) {
    if (threadIdx.x == 0 && blockIdx.x == 0) {
        int run = 0;
        for (int i = 0; i < nch; i++) { int t = g_chunksum[i]; g_chunksum[i] = run; run += t; }
    }
}
__global__ void k_scan3() {
    int tid = threadIdx.x;
    int t = blockIdx.x * 1024 + tid;
    if (t < NN) {
        int inc = g_offsets[t + 1] + g_chunksum[blockIdx.x];
        g_offsets[t + 1] = inc;
        g_cursor[t] = inc - g_counts[t];
    }
    if (t == 0) g_offsets[0] = 0;
}
__global__ void k_scatter(const int* __restrict__ src, const int* __restrict__ dst) {
    int e4 = (blockIdx.x * blockDim.x + threadIdx.x) * 4;
    if (e4 < EE) {
        int4 s4 = *(const int4*)(src + e4);
        int4 d4 = *(const int4*)(dst + e4);
        int p0 = atomicAdd(&g_cursor[d4.x], 1); g_csr_src[p0] = s4.x;
        int p1 = atomicAdd(&g_cursor[d4.y], 1); g_csr_src[p1] = s4.y;
        int p2 = atomicAdd(&g_cursor[d4.z], 1); g_csr_src[p2] = s4.z;
        int p3 = atomicAdd(&g_cursor[d4.w], 1); g_csr_src[p3] = s4.w;
    }
}

// ---------------- fused score + online-softmax + agg (2-edge pairing) ----------------
__global__ void __launch_bounds__(256)
k_agg(const float* __restrict__ feat) {
    int warp = (blockIdx.x * blockDim.x + threadIdx.x) >> 5;
    int lane = threadIdx.x & 31;
    if (warp >= NN) return;
    const int n = warp;
    const int start = g_offsets[n];
    const int end = g_offsets[n + 1];
    const int hsel = lane & 3;
    float* zhp = g_zh + (size_t)n * 512 + lane * 4;
    float* zlp = g_zl + (size_t)n * 512 + lane * 4;

    if (start == end) {  // z = 0 -> out = bias
        float4 zz = make_float4(0.f, 0.f, 0.f, 0.f);
#pragma unroll
        for (int h = 0; h < 4; h++) {
            *(float4*)(zhp + h * FIN) = zz;
            *(float4*)(zlp + h * FIN) = zz;
        }
        return;
    }

    float4 fd = *(const float4*)(feat + n * FIN + lane * 4);
    float4 c0 = *(const float4*)(g_wc + 0 * FIN + lane * 4);
    float4 c1 = *(const float4*)(g_wc + 1 * FIN + lane * 4);
    float4 c2 = *(const float4*)(g_wc + 2 * FIN + lane * 4);
    float4 c3 = *(const float4*)(g_wc + 3 * FIN + lane * 4);
    c0.x *= fd.x; c0.y *= fd.y; c0.z *= fd.z; c0.w *= fd.w;
    c1.x *= fd.x; c1.y *= fd.y; c1.z *= fd.z; c1.w *= fd.w;
    c2.x *= fd.x; c2.y *= fd.y; c2.z *= fd.z; c2.w *= fd.w;
    c3.x *= fd.x; c3.y *= fd.y; c3.z *= fd.z; c3.w *= fd.w;
    float er_s = __ldg(g_er2 + n * 4 + hsel);

    float m = -3.0e38f, s = 0.f;
    float4 z0 = make_float4(0.f, 0.f, 0.f, 0.f);
    float4 z1 = z0, z2 = z0, z3 = z0;

    int idx = start;
    for (; idx + 1 < end; idx += 2) {
        int sa = __ldg(g_csr_src + idx);
        int sb = __ldg(g_csr_src + idx + 1);
        float4 fa = *(const float4*)(feat + sa * FIN + lane * 4);
        float4 fb = *(const float4*)(feat + sb * FIN + lane * 4);
        float ela = __ldg(g_el2 + sa * 4 + hsel);
        float elb = __ldg(g_el2 + sb * 4 + hsel);

        float pa0 = fa.x * c0.x + fa.y * c0.y + fa.z * c0.z + fa.w * c0.w;
        float pa1 = fa.x * c1.x + fa.y * c1.y + fa.z * c1.z + fa.w * c1.w;
        float pa2 = fa.x * c2.x + fa.y * c2.y + fa.z * c2.z + fa.w * c2.w;
        float pa3 = fa.x * c3.x + fa.y * c3.y + fa.z * c3.z + fa.w * c3.w;
        float pb0 = fb.x * c0.x + fb.y * c0.y + fb.z * c0.z + fb.w * c0.w;
        float pb1 = fb.x * c1.x + fb.y * c1.y + fb.z * c1.z + fb.w * c1.w;
        float pb2 = fb.x * c2.x + fb.y * c2.y + fb.z * c2.z + fb.w * c2.w;
        float pb3 = fb.x * c3.x + fb.y * c3.y + fb.z * c3.z + fb.w * c3.w;

        // two independent fold+butterfly chains, interleaved for ILP
        float ua01 = (lane & 1) ? pa1 : pa0, ta01 = (lane & 1) ? pa0 : pa1;
        float ub01 = (lane & 1) ? pb1 : pb0, tb01 = (lane & 1) ? pb0 : pb1;
        ua01 += __shfl_xor_sync(0xffffffffu, ta01, 1);
        ub01 += __shfl_xor_sync(0xffffffffu, tb01, 1);
        float ua23 = (lane & 1) ? pa3 : pa2, ta23 = (lane & 1) ? pa2 : pa3;
        float ub23 = (lane & 1) ? pb3 : pb2, tb23 = (lane & 1) ? pb2 : pb3;
        ua23 += __shfl_xor_sync(0xffffffffu, ta23, 1);
        ub23 += __shfl_xor_sync(0xffffffffu, tb23, 1);
        float va = (lane & 2) ? ua23 : ua01, ta = (lane & 2) ? ua01 : ua23;
        float vb = (lane & 2) ? ub23 : ub01, tb = (lane & 2) ? ub01 : ub23;
        va += __shfl_xor_sync(0xffffffffu, ta, 2);
        vb += __shfl_xor_sync(0xffffffffu, tb, 2);
        va += __shfl_xor_sync(0xffffffffu, va, 4);
        vb += __shfl_xor_sync(0xffffffffu, vb, 4);
        va += __shfl_xor_sync(0xffffffffu, va, 8);
        vb += __shfl_xor_sync(0xffffffffu, vb, 8);
        va += __shfl_xor_sync(0xffffffffu, va, 16);
        vb += __shfl_xor_sync(0xffffffffu, vb, 16);

        float ea = va + ela + er_s;
        float eb = vb + elb + er_s;
        float mn = fmaxf(m, fmaxf(ea, eb));

        if (__any_sync(0xffffffffu, mn > m)) {
            float sc = __expf(m - mn);
            s *= sc;
            float s0 = __shfl_sync(0xffffffffu, sc, 0);
            float s1 = __shfl_sync(0xffffffffu, sc, 1);
            float s2 = __shfl_sync(0xffffffffu, sc, 2);
            float s3 = __shfl_sync(0xffffffffu, sc, 3);
            z0.x *= s0; z0.y *= s0; z0.z *= s0; z0.w *= s0;
            z1.x *= s1; z1.y *= s1; z1.z *= s1; z1.w *= s1;
            z2.x *= s2; z2.y *= s2; z2.z *= s2; z2.w *= s2;
            z3.x *= s3; z3.y *= s3; z3.z *= s3; z3.w *= s3;
        }
        m = mn;
        float wa = __expf(ea - mn);
        float wb = __expf(eb - mn);
        s += wa + wb;

        float wa0 = __shfl_sync(0xffffffffu, wa, 0);
        float wa1 = __shfl_sync(0xffffffffu, wa, 1);
        float wa2 = __shfl_sync(0xffffffffu, wa, 2);
        float wa3 = __shfl_sync(0xffffffffu, wa, 3);
        float wb0 = __shfl_sync(0xffffffffu, wb, 0);
        float wb1 = __shfl_sync(0xffffffffu, wb, 1);
        float wb2 = __shfl_sync(0xffffffffu, wb, 2);
        float wb3 = __shfl_sync(0xffffffffu, wb, 3);

        z0.x += wa0 * fa.x + wb0 * fb.x; z0.y += wa0 * fa.y + wb0 * fb.y;
        z0.z += wa0 * fa.z + wb0 * fb.z; z0.w += wa0 * fa.w + wb0 * fb.w;
        z1.x += wa1 * fa.x + wb1 * fb.x; z1.y += wa1 * fa.y + wb1 * fb.y;
        z1.z += wa1 * fa.z + wb1 * fb.z; z1.w += wa1 * fa.w + wb1 * fb.w;
        z2.x += wa2 * fa.x + wb2 * fb.x; z2.y += wa2 * fa.y + wb2 * fb.y;
        z2.z += wa2 * fa.z + wb2 * fb.z; z2.w += wa2 * fa.w + wb2 * fb.w;
        z3.x += wa3 * fa.x + wb3 * fb.x; z3.y += wa3 * fa.y + wb3 * fb.y;
        z3.z += wa3 * fa.z + wb3 * fb.z; z3.w += wa3 * fa.w + wb3 * fb.w;
    }

    if (idx < end) {  // remainder edge
        int sa = __ldg(g_csr_src + idx);
        float4 fa = *(const float4*)(feat + sa * FIN + lane * 4);
        float ela = __ldg(g_el2 + sa * 4 + hsel);
        float pa0 = fa.x * c0.x + fa.y * c0.y + fa.z * c0.z + fa.w * c0.w;
        float pa1 = fa.x * c1.x + fa.y * c1.y + fa.z * c1.z + fa.w * c1.w;
        float pa2 = fa.x * c2.x + fa.y * c2.y + fa.z * c2.z + fa.w * c2.w;
        float pa3 = fa.x * c3.x + fa.y * c3.y + fa.z * c3.z + fa.w * c3.w;
        float ua01 = (lane & 1) ? pa1 : pa0, ta01 = (lane & 1) ? pa0 : pa1;
        ua01 += __shfl_xor_sync(0xffffffffu, ta01, 1);
        float ua23 = (lane & 1) ? pa3 : pa2, ta23 = (lane & 1) ? pa2 : pa3;
        ua23 += __shfl_xor_sync(0xffffffffu, ta23, 1);
        float va = (lane & 2) ? ua23 : ua01, ta = (lane & 2) ? ua01 : ua23;
        va += __shfl_xor_sync(0xffffffffu, ta, 2);
        va += __shfl_xor_sync(0xffffffffu, va, 4);
        va += __shfl_xor_sync(0xffffffffu, va, 8);
        va += __shfl_xor_sync(0xffffffffu, va, 16);
        float ea = va + ela + er_s;
        float mn = fmaxf(m, ea);
        if (__any_sync(0xffffffffu, mn > m)) {
            float sc = __expf(m - mn);
            s *= sc;
            float s0 = __shfl_sync(0xffffffffu, sc, 0);
            float s1 = __shfl_sync(0xffffffffu, sc, 1);
            float s2 = __shfl_sync(0xffffffffu, sc, 2);
            float s3 = __shfl_sync(0xffffffffu, sc, 3);
            z0.x *= s0; z0.y *= s0; z0.z *= s0; z0.w *= s0;
            z1.x *= s1; z1.y *= s1; z1.z *= s1; z1.w *= s1;
            z2.x *= s2; z2.y *= s2; z2.z *= s2; z2.w *= s2;
            z3.x *= s3; z3.y *= s3; z3.z *= s3; z3.w *= s3;
        }
        m = mn;
        float wa = __expf(ea - mn);
        s += wa;
        float wa0 = __shfl_sync(0xffffffffu, wa, 0);
        float wa1 = __shfl_sync(0xffffffffu, wa, 1);
        float wa2 = __shfl_sync(0xffffffffu, wa, 2);
        float wa3 = __shfl_sync(0xffffffffu, wa, 3);
        z0.x += wa0 * fa.x; z0.y += wa0 * fa.y; z0.z += wa0 * fa.z; z0.w += wa0 * fa.w;
        z1.x += wa1 * fa.x; z1.y += wa1 * fa.y; z1.z += wa1 * fa.z; z1.w += wa1 * fa.w;
        z2.x += wa2 * fa.x; z2.y += wa2 * fa.y; z2.z += wa2 * fa.z; z2.w += wa2 * fa.w;
        z3.x += wa3 * fa.x; z3.y += wa3 * fa.y; z3.z += wa3 * fa.z; z3.w += wa3 * fa.w;
    }

    float rinv = 1.f / s;
    float r0 = __shfl_sync(0xffffffffu, rinv, 0);
    float r1 = __shfl_sync(0xffffffffu, rinv, 1);
    float r2 = __shfl_sync(0xffffffffu, rinv, 2);
    float r3 = __shfl_sync(0xffffffffu, rinv, 3);

    float4 zz[4];
    zz[0] = make_float4(z0.x * r0, z0.y * r0, z0.z * r0, z0.w * r0);
    zz[1] = make_float4(z1.x * r1, z1.y * r1, z1.z * r1, z1.w * r1);
    zz[2] = make_float4(z2.x * r2, z2.y * r2, z2.z * r2, z2.w * r2);
    zz[3] = make_float4(z3.x * r3, z3.y * r3, z3.z * r3, z3.w * r3);
#pragma unroll
    for (int h = 0; h < 4; h++) {
        float4 hi4, lo4;
        hi4.x = tf32_rna(zz[h].x); lo4.x = tf32_rna(zz[h].x - hi4.x);
        hi4.y = tf32_rna(zz[h].y); lo4.y = tf32_rna(zz[h].y - hi4.y);
        hi4.z = tf32_rna(zz[h].z); lo4.z = tf32_rna(zz[h].z - hi4.z);
        hi4.w = tf32_rna(zz[h].w); lo4.w = tf32_rna(zz[h].w - hi4.w);
        *(float4*)(zhp + h * FIN) = hi4;
        *(float4*)(zlp + h * FIN) = lo4;
    }
}

// ---------------- tensor-core split-tf32 GEMM with smem staging ----------------
// grid (HH, 391), block 256 (8 warps). Warp w: channels (w&3)*16.., node panel (w>>2)*64.
// K processed in 4 chunks of 32 staged in smem. out^T = W_h @ z_h^T per head.
__global__ void __launch_bounds__(256)
k_tc(const float* __restrict__ bias, float* __restrict__ out) {
    __shared__ float zsh[128][36];
    __shared__ float zsl[128][36];
    const int h = blockIdx.x;
    const int nBase = blockIdx.y * 128;
    const int tid = threadIdx.x;
    const int w = tid >> 5;
    const int lane = tid & 31;
    const int g = lane >> 2;        // 0..7
    const int t4 = lane & 3;        // 0..3
    const int cg = w & 3;           // channel group: 16 ch
    const int np = w >> 2;          // node panel: 64 nodes

    float acc[8][4];
#pragma unroll
    for (int i = 0; i < 8; i++)
#pragma unroll
        for (int j = 0; j < 4; j++) acc[i][j] = 0.f;

    const float* wh = g_wsh + (size_t)(h * FO + cg * 16) * FIN;
    const float* wl = g_wsl + (size_t)(h * FO + cg * 16) * FIN;

    for (int kc = 0; kc < 4; kc++) {
        // cooperative stage: z chunk [128 nodes][32 k] hi+lo, coalesced float4
        __syncthreads();
#pragma unroll
        for (int i = 0; i < 4; i++) {
            int slot = tid + i * 256;          // 0..1023
            int row = slot >> 3;
            int c4 = (slot & 7) * 4;
            size_t gi = (size_t)(nBase + row) * 512 + h * 128 + kc * 32 + c4;
            *(float4*)(&zsh[row][c4]) = *(const float4*)(g_zh + gi);
            *(float4*)(&zsl[row][c4]) = *(const float4*)(g_zl + gi);
        }
        __syncthreads();

#pragma unroll
        for (int kf = 0; kf < 4; kf++) {
            const int k0 = kc * 32 + kf * 8;
            uint32_t ah0 = __float_as_uint(__ldg(wh + (g)     * FIN + k0 + t4));
            uint32_t ah1 = __float_as_uint(__ldg(wh + (g + 8) * FIN + k0 + t4));
            uint32_t ah2 = __float_as_uint(__ldg(wh + (g)     * FIN + k0 + t4 + 4));
            uint32_t ah3 = __float_as_uint(__ldg(wh + (g + 8) * FIN + k0 + t4 + 4));
            uint32_t al0 = __float_as_uint(__ldg(wl + (g)     * FIN + k0 + t4));
            uint32_t al1 = __float_as_uint(__ldg(wl + (g + 8) * FIN + k0 + t4));
            uint32_t al2 = __float_as_uint(__ldg(wl + (g)     * FIN + k0 + t4 + 4));
            uint32_t al3 = __float_as_uint(__ldg(wl + (g + 8) * FIN + k0 + t4 + 4));
            const int ks = kf * 8;
#pragma unroll
            for (int nf = 0; nf < 8; nf++) {
                int row = np * 64 + nf * 8 + g;
                uint32_t bh0 = __float_as_uint(zsh[row][ks + t4]);
                uint32_t bh1 = __float_as_uint(zsh[row][ks + t4 + 4]);
                uint32_t bl0 = __float_as_uint(zsl[row][ks + t4]);
                uint32_t bl1 = __float_as_uint(zsl[row][ks + t4 + 4]);
                mma_tf32(acc[nf][0], acc[nf][1], acc[nf][2], acc[nf][3],
                         ah0, ah1, ah2, ah3, bh0, bh1);
                mma_tf32(acc[nf][0], acc[nf][1], acc[nf][2], acc[nf][3],
                         ah0, ah1, ah2, ah3, bl0, bl1);
                mma_tf32(acc[nf][0], acc[nf][1], acc[nf][2], acc[nf][3],
                         al0, al1, al2, al3, bh0, bh1);
            }
        }
    }

    // store: D[m=ch][n=node]; c0=D[g][2t4], c1=D[g][2t4+1], c2=D[g+8][2t4], c3=D[g+8][2t4+1]
    int ch  = h * FO + cg * 16 + g;
    int ch8 = ch + 8;
    float bg  = __ldg(bias + ch);
    float bg8 = __ldg(bias + ch8);
#pragma unroll
    for (int nf = 0; nf < 8; nf++) {
        int n0 = nBase + np * 64 + nf * 8 + 2 * t4;
        int n1 = n0 + 1;
        if (n0 < NN) {
            out[(size_t)n0 * NOUT + ch]  = acc[nf][0] + bg;
            out[(size_t)n0 * NOUT + ch8] = acc[nf][2] + bg8;
        }
        if (n1 < NN) {
            out[(size_t)n1 * NOUT + ch]  = acc[nf][1] + bg;
            out[(size_t)n1 * NOUT + ch8] = acc[nf][3] + bg8;
        }
    }
}

// ---------------- launch ----------------
extern "C" void kernel_launch(void* const* d_in, const int* in_sizes, int n_in,
                              void* d_out, int out_size) {
    const float* feat  = (const float*)d_in[0];
    const int*   src   = (const int*)d_in[1];
    const int*   dst   = (const int*)d_in[2];
    const float* fc_w  = (const float*)d_in[3];
    const float* al    = (const float*)d_in[4];
    const float* ar    = (const float*)d_in[5];
    const float* al1   = (const float*)d_in[6];
    const float* ar1   = (const float*)d_in[7];
    const float* bias  = (const float*)d_in[8];
    float* out = (float*)d_out;

    const int nch = (NN + 1023) / 1024;  // 49

    k_prep<<<(NN + 255) / 256, 256>>>(al, ar, al1, ar1, fc_w);
    k_hist<<<(EE / 4 + 255) / 256, 256>>>(dst);
    k_node<<<(NN * 32 + 255) / 256, 256>>>(feat, al1, ar1);
    k_scan1<<<nch, 1024>>>();
    k_scan2<<<1, 32>>>(nch);
    k_scan3<<<nch, 1024>>>();
    k_scatter<<<(EE / 4 + 255) / 256, 256>>>(src, dst);
    k_agg<<<(NN * 32 + 255) / 256, 256>>>(feat);
    k_tc<<<dim3(HH, NR / 128), 256>>>(bias, out);
}

// round 9
// speedup vs baseline: 1.3599x; 1.0947x over previous
#include <cuda_runtime.h>
#include <cstdint>

#define NN 50000
#define NR 50048      // 391 * 128
#define EE 800000
#define FIN 128
#define HH 4
#define FO 64
#define NOUT 256
#define PREPN 50176   // max(NN, NOUT*FIN) rounded to 256

// ---- static scratch ----
__device__ float g_z[(size_t)NR * 512];   // aggregated features [n][h][128] fp32
__device__ float g_wsh[NOUT * FIN];       // W tf32-hi
__device__ float g_wsl[NOUT * FIN];       // W tf32-lo
__device__ float g_el2[NN * HH];
__device__ float g_er2[NN * HH];
__device__ float g_wc[HH * FIN];
__device__ int   g_counts[NN];
__device__ int   g_offsets[NN + 1];
__device__ int   g_cursor[NN];
__device__ int   g_csr_src[EE];
__device__ int   g_chunksum[64];

// ---- tf32 helpers ----
__device__ __forceinline__ float tf32_rna(float x) {
    uint32_t r;
    asm("cvt.rna.tf32.f32 %0, %1;" : "=r"(r) : "f"(x));
    return __uint_as_float(r);
}
__device__ __forceinline__ void mma_tf32(float& d0, float& d1, float& d2, float& d3,
                                         uint32_t a0, uint32_t a1, uint32_t a2, uint32_t a3,
                                         uint32_t b0, uint32_t b1) {
    asm("mma.sync.aligned.m16n8k8.row.col.f32.tf32.tf32.f32 "
        "{%0,%1,%2,%3}, {%4,%5,%6,%7}, {%8,%9}, {%0,%1,%2,%3};"
        : "+f"(d0), "+f"(d1), "+f"(d2), "+f"(d3)
        : "r"(a0), "r"(a1), "r"(a2), "r"(a3), "r"(b0), "r"(b1));
}

// ---------------- prep: wc + W split + zero counts ----------------
// NOTE: grid must cover max(NN, NOUT*FIN) — counts zeroing is replay-critical.
__global__ void k_prep(const float* __restrict__ al, const float* __restrict__ ar,
                       const float* __restrict__ al1, const float* __restrict__ ar1,
                       const float* __restrict__ W) {
    int i = blockIdx.x * blockDim.x + threadIdx.x;
    if (i < HH * FIN) g_wc[i] = al[i] * ar[i] - 2.0f * al1[i] * ar1[i];
    if (i < NOUT * FIN) {
        float w = W[i];
        float hi = tf32_rna(w);
        g_wsh[i] = hi;
        g_wsl[i] = tf32_rna(w - hi);
    }
    if (i < NN) g_counts[i] = 0;
}

// ---------------- per-node el2/er2 ----------------
__global__ void k_node(const float* __restrict__ feat,
                       const float* __restrict__ al1, const float* __restrict__ ar1) {
    int warp = (blockIdx.x * blockDim.x + threadIdx.x) >> 5;
    int lane = threadIdx.x & 31;
    if (warp >= NN) return;
    float4 f = *(const float4*)(feat + warp * FIN + lane * 4);
    float q0 = f.x * f.x, q1 = f.y * f.y, q2 = f.z * f.z, q3 = f.w * f.w;
    float pl[4], pr[4];
#pragma unroll
    for (int h = 0; h < 4; h++) {
        float4 a = *(const float4*)(al1 + h * FIN + lane * 4);
        float4 b = *(const float4*)(ar1 + h * FIN + lane * 4);
        pl[h] = q0 * a.x * a.x + q1 * a.y * a.y + q2 * a.z * a.z + q3 * a.w * a.w;
        pr[h] = q0 * b.x * b.x + q1 * b.y * b.y + q2 * b.z * b.z + q3 * b.w * b.w;
    }
#pragma unroll
    for (int off = 16; off; off >>= 1) {
#pragma unroll
        for (int h = 0; h < 4; h++) {
            pl[h] += __shfl_xor_sync(0xffffffffu, pl[h], off);
            pr[h] += __shfl_xor_sync(0xffffffffu, pr[h], off);
        }
    }
    if (lane == 0) {
        *(float4*)(g_el2 + warp * 4) = make_float4(pl[0], pl[1], pl[2], pl[3]);
        *(float4*)(g_er2 + warp * 4) = make_float4(pr[0], pr[1], pr[2], pr[3]);
    }
}

// ---------------- CSR build ----------------
__global__ void k_hist(const int* __restrict__ dst) {
    int e4 = (blockIdx.x * blockDim.x + threadIdx.x) * 4;
    if (e4 < EE) {
        int4 d4 = *(const int4*)(dst + e4);
        atomicAdd(&g_counts[d4.x], 1);
        atomicAdd(&g_counts[d4.y], 1);
        atomicAdd(&g_counts[d4.z], 1);
        atomicAdd(&g_counts[d4.w], 1);
    }
}

__global__ void k_scan1() {
    __shared__ int wsum[32];
    int tid = threadIdx.x;
    int t = blockIdx.x * 1024 + tid;
    int lane = tid & 31, wid = tid >> 5;
    int x = (t < NN) ? g_counts[t] : 0;
#pragma unroll
    for (int off = 1; off < 32; off <<= 1) {
        int y = __shfl_up_sync(0xffffffffu, x, off);
        if (lane >= off) x += y;
    }
    if (lane == 31) wsum[wid] = x;
    __syncthreads();
    if (wid == 0) {
        int ws = wsum[lane];
#pragma unroll
        for (int off = 1; off < 32; off <<= 1) {
            int y = __shfl_up_sync(0xffffffffu, ws, off);
            if (lane >= off) ws += y;
        }
        wsum[lane] = ws;
    }
    __syncthreads();
    if (wid > 0) x += wsum[wid - 1];
    if (t < NN) g_offsets[t + 1] = x;
    if (tid == 1023) g_chunksum[blockIdx.x] = x;
}
__global__ void k_scan2(int nch) {
    if (threadIdx.x == 0 && blockIdx.x == 0) {
        int run = 0;
        for (int i = 0; i < nch; i++) { int t = g_chunksum[i]; g_chunksum[i] = run; run += t; }
    }
}
__global__ void k_scan3() {
    int tid = threadIdx.x;
    int t = blockIdx.x * 1024 + tid;
    if (t < NN) {
        int inc = g_offsets[t + 1] + g_chunksum[blockIdx.x];
        g_offsets[t + 1] = inc;
        g_cursor[t] = inc - g_counts[t];
    }
    if (t == 0) g_offsets[0] = 0;
}
__global__ void k_scatter(const int* __restrict__ src, const int* __restrict__ dst) {
    int e4 = (blockIdx.x * blockDim.x + threadIdx.x) * 4;
    if (e4 < EE) {
        int4 s4 = *(const int4*)(src + e4);
        int4 d4 = *(const int4*)(dst + e4);
        int p0 = atomicAdd(&g_cursor[d4.x], 1); g_csr_src[p0] = s4.x;
        int p1 = atomicAdd(&g_cursor[d4.y], 1); g_csr_src[p1] = s4.y;
        int p2 = atomicAdd(&g_cursor[d4.z], 1); g_csr_src[p2] = s4.z;
        int p3 = atomicAdd(&g_cursor[d4.w], 1); g_csr_src[p3] = s4.w;
    }
}

// ---------------- fused score + online-softmax + agg (2-edge pairing) ----------------
__global__ void __launch_bounds__(256)
k_agg(const float* __restrict__ feat) {
    int warp = (blockIdx.x * blockDim.x + threadIdx.x) >> 5;
    int lane = threadIdx.x & 31;
    if (warp >= NN) return;
    const int n = warp;
    const int start = g_offsets[n];
    const int end = g_offsets[n + 1];
    const int hsel = lane & 3;
    float* zp = g_z + (size_t)n * 512 + lane * 4;

    if (start == end) {  // z = 0 -> out = bias
        float4 zz = make_float4(0.f, 0.f, 0.f, 0.f);
#pragma unroll
        for (int h = 0; h < 4; h++) *(float4*)(zp + h * FIN) = zz;
        return;
    }

    float4 fd = *(const float4*)(feat + n * FIN + lane * 4);
    float4 c0 = *(const float4*)(g_wc + 0 * FIN + lane * 4);
    float4 c1 = *(const float4*)(g_wc + 1 * FIN + lane * 4);
    float4 c2 = *(const float4*)(g_wc + 2 * FIN + lane * 4);
    float4 c3 = *(const float4*)(g_wc + 3 * FIN + lane * 4);
    c0.x *= fd.x; c0.y *= fd.y; c0.z *= fd.z; c0.w *= fd.w;
    c1.x *= fd.x; c1.y *= fd.y; c1.z *= fd.z; c1.w *= fd.w;
    c2.x *= fd.x; c2.y *= fd.y; c2.z *= fd.z; c2.w *= fd.w;
    c3.x *= fd.x; c3.y *= fd.y; c3.z *= fd.z; c3.w *= fd.w;
    float er_s = __ldg(g_er2 + n * 4 + hsel);

    float m = -3.0e38f, s = 0.f;
    float4 z0 = make_float4(0.f, 0.f, 0.f, 0.f);
    float4 z1 = z0, z2 = z0, z3 = z0;

    int idx = start;
    for (; idx + 1 < end; idx += 2) {
        int sa = __ldg(g_csr_src + idx);
        int sb = __ldg(g_csr_src + idx + 1);
        float4 fa = *(const float4*)(feat + sa * FIN + lane * 4);
        float4 fb = *(const float4*)(feat + sb * FIN + lane * 4);
        float ela = __ldg(g_el2 + sa * 4 + hsel);
        float elb = __ldg(g_el2 + sb * 4 + hsel);

        float pa0 = fa.x * c0.x + fa.y * c0.y + fa.z * c0.z + fa.w * c0.w;
        float pa1 = fa.x * c1.x + fa.y * c1.y + fa.z * c1.z + fa.w * c1.w;
        float pa2 = fa.x * c2.x + fa.y * c2.y + fa.z * c2.z + fa.w * c2.w;
        float pa3 = fa.x * c3.x + fa.y * c3.y + fa.z * c3.z + fa.w * c3.w;
        float pb0 = fb.x * c0.x + fb.y * c0.y + fb.z * c0.z + fb.w * c0.w;
        float pb1 = fb.x * c1.x + fb.y * c1.y + fb.z * c1.z + fb.w * c1.w;
        float pb2 = fb.x * c2.x + fb.y * c2.y + fb.z * c2.z + fb.w * c2.w;
        float pb3 = fb.x * c3.x + fb.y * c3.y + fb.z * c3.z + fb.w * c3.w;

        float ua01 = (lane & 1) ? pa1 : pa0, ta01 = (lane & 1) ? pa0 : pa1;
        float ub01 = (lane & 1) ? pb1 : pb0, tb01 = (lane & 1) ? pb0 : pb1;
        ua01 += __shfl_xor_sync(0xffffffffu, ta01, 1);
        ub01 += __shfl_xor_sync(0xffffffffu, tb01, 1);
        float ua23 = (lane & 1) ? pa3 : pa2, ta23 = (lane & 1) ? pa2 : pa3;
        float ub23 = (lane & 1) ? pb3 : pb2, tb23 = (lane & 1) ? pb2 : pb3;
        ua23 += __shfl_xor_sync(0xffffffffu, ta23, 1);
        ub23 += __shfl_xor_sync(0xffffffffu, tb23, 1);
        float va = (lane & 2) ? ua23 : ua01, ta = (lane & 2) ? ua01 : ua23;
        float vb = (lane & 2) ? ub23 : ub01, tb = (lane & 2) ? ub01 : ub23;
        va += __shfl_xor_sync(0xffffffffu, ta, 2);
        vb += __shfl_xor_sync(0xffffffffu, tb, 2);
        va += __shfl_xor_sync(0xffffffffu, va, 4);
        vb += __shfl_xor_sync(0xffffffffu, vb, 4);
        va += __shfl_xor_sync(0xffffffffu, va, 8);
        vb += __shfl_xor_sync(0xffffffffu, vb, 8);
        va += __shfl_xor_sync(0xffffffffu, va, 16);
        vb += __shfl_xor_sync(0xffffffffu, vb, 16);

        float ea = va + ela + er_s;
        float eb = vb + elb + er_s;
        float mn = fmaxf(m, fmaxf(ea, eb));

        if (__any_sync(0xffffffffu, mn > m)) {
            float sc = __expf(m - mn);
            s *= sc;
            float s0 = __shfl_sync(0xffffffffu, sc, 0);
            float s1 = __shfl_sync(0xffffffffu, sc, 1);
            float s2 = __shfl_sync(0xffffffffu, sc, 2);
            float s3 = __shfl_sync(0xffffffffu, sc, 3);
            z0.x *= s0; z0.y *= s0; z0.z *= s0; z0.w *= s0;
            z1.x *= s1; z1.y *= s1; z1.z *= s1; z1.w *= s1;
            z2.x *= s2; z2.y *= s2; z2.z *= s2; z2.w *= s2;
            z3.x *= s3; z3.y *= s3; z3.z *= s3; z3.w *= s3;
        }
        m = mn;
        float wa = __expf(ea - mn);
        float wb = __expf(eb - mn);
        s += wa + wb;

        float wa0 = __shfl_sync(0xffffffffu, wa, 0);
        float wa1 = __shfl_sync(0xffffffffu, wa, 1);
        float wa2 = __shfl_sync(0xffffffffu, wa, 2);
        float wa3 = __shfl_sync(0xffffffffu, wa, 3);
        float wb0 = __shfl_sync(0xffffffffu, wb, 0);
        float wb1 = __shfl_sync(0xffffffffu, wb, 1);
        float wb2 = __shfl_sync(0xffffffffu, wb, 2);
        float wb3 = __shfl_sync(0xffffffffu, wb, 3);

        z0.x += wa0 * fa.x + wb0 * fb.x; z0.y += wa0 * fa.y + wb0 * fb.y;
        z0.z += wa0 * fa.z + wb0 * fb.z; z0.w += wa0 * fa.w + wb0 * fb.w;
        z1.x += wa1 * fa.x + wb1 * fb.x; z1.y += wa1 * fa.y + wb1 * fb.y;
        z1.z += wa1 * fa.z + wb1 * fb.z; z1.w += wa1 * fa.w + wb1 * fb.w;
        z2.x += wa2 * fa.x + wb2 * fb.x; z2.y += wa2 * fa.y + wb2 * fb.y;
        z2.z += wa2 * fa.z + wb2 * fb.z; z2.w += wa2 * fa.w + wb2 * fb.w;
        z3.x += wa3 * fa.x + wb3 * fb.x; z3.y += wa3 * fa.y + wb3 * fb.y;
        z3.z += wa3 * fa.z + wb3 * fb.z; z3.w += wa3 * fa.w + wb3 * fb.w;
    }

    if (idx < end) {  // remainder edge
        int sa = __ldg(g_csr_src + idx);
        float4 fa = *(const float4*)(feat + sa * FIN + lane * 4);
        float ela = __ldg(g_el2 + sa * 4 + hsel);
        float pa0 = fa.x * c0.x + fa.y * c0.y + fa.z * c0.z + fa.w * c0.w;
        float pa1 = fa.x * c1.x + fa.y * c1.y + fa.z * c1.z + fa.w * c1.w;
        float pa2 = fa.x * c2.x + fa.y * c2.y + fa.z * c2.z + fa.w * c2.w;
        float pa3 = fa.x * c3.x + fa.y * c3.y + fa.z * c3.z + fa.w * c3.w;
        float ua01 = (lane & 1) ? pa1 : pa0, ta01 = (lane & 1) ? pa0 : pa1;
        ua01 += __shfl_xor_sync(0xffffffffu, ta01, 1);
        float ua23 = (lane & 1) ? pa3 : pa2, ta23 = (lane & 1) ? pa2 : pa3;
        ua23 += __shfl_xor_sync(0xffffffffu, ta23, 1);
        float va = (lane & 2) ? ua23 : ua01, ta = (lane & 2) ? ua01 : ua23;
        va += __shfl_xor_sync(0xffffffffu, ta, 2);
        va += __shfl_xor_sync(0xffffffffu, va, 4);
        va += __shfl_xor_sync(0xffffffffu, va, 8);
        va += __shfl_xor_sync(0xffffffffu, va, 16);
        float ea = va + ela + er_s;
        float mn = fmaxf(m, ea);
        if (__any_sync(0xffffffffu, mn > m)) {
            float sc = __expf(m - mn);
            s *= sc;
            float s0 = __shfl_sync(0xffffffffu, sc, 0);
            float s1 = __shfl_sync(0xffffffffu, sc, 1);
            float s2 = __shfl_sync(0xffffffffu, sc, 2);
            float s3 = __shfl_sync(0xffffffffu, sc, 3);
            z0.x *= s0; z0.y *= s0; z0.z *= s0; z0.w *= s0;
            z1.x *= s1; z1.y *= s1; z1.z *= s1; z1.w *= s1;
            z2.x *= s2; z2.y *= s2; z2.z *= s2; z2.w *= s2;
            z3.x *= s3; z3.y *= s3; z3.z *= s3; z3.w *= s3;
        }
        m = mn;
        float wa = __expf(ea - mn);
        s += wa;
        float wa0 = __shfl_sync(0xffffffffu, wa, 0);
        float wa1 = __shfl_sync(0xffffffffu, wa, 1);
        float wa2 = __shfl_sync(0xffffffffu, wa, 2);
        float wa3 = __shfl_sync(0xffffffffu, wa, 3);
        z0.x += wa0 * fa.x; z0.y += wa0 * fa.y; z0.z += wa0 * fa.z; z0.w += wa0 * fa.w;
        z1.x += wa1 * fa.x; z1.y += wa1 * fa.y; z1.z += wa1 * fa.z; z1.w += wa1 * fa.w;
        z2.x += wa2 * fa.x; z2.y += wa2 * fa.y; z2.z += wa2 * fa.z; z2.w += wa2 * fa.w;
        z3.x += wa3 * fa.x; z3.y += wa3 * fa.y; z3.z += wa3 * fa.z; z3.w += wa3 * fa.w;
    }

    float rinv = 1.f / s;
    float r0 = __shfl_sync(0xffffffffu, rinv, 0);
    float r1 = __shfl_sync(0xffffffffu, rinv, 1);
    float r2 = __shfl_sync(0xffffffffu, rinv, 2);
    float r3 = __shfl_sync(0xffffffffu, rinv, 3);

    *(float4*)(zp + 0 * FIN) = make_float4(z0.x * r0, z0.y * r0, z0.z * r0, z0.w * r0);
    *(float4*)(zp + 1 * FIN) = make_float4(z1.x * r1, z1.y * r1, z1.z * r1, z1.w * r1);
    *(float4*)(zp + 2 * FIN) = make_float4(z2.x * r2, z2.y * r2, z2.z * r2, z2.w * r2);
    *(float4*)(zp + 3 * FIN) = make_float4(z3.x * r3, z3.y * r3, z3.z * r3, z3.w * r3);
}

// ---------------- tensor-core split-tf32 GEMM, split-at-staging ----------------
// grid (HH, 391), block 256 (8 warps). Warp w: channels (w&3)*16.., node panel (w>>2)*64.
// z read once as fp32; tf32 hi/lo derived during smem store (once per element).
__global__ void __launch_bounds__(256)
k_tc(const float* __restrict__ bias, float* __restrict__ out) {
    __shared__ float zsh[128][36];
    __shared__ float zsl[128][36];
    const int h = blockIdx.x;
    const int nBase = blockIdx.y * 128;
    const int tid = threadIdx.x;
    const int w = tid >> 5;
    const int lane = tid & 31;
    const int g = lane >> 2;        // 0..7
    const int t4 = lane & 3;        // 0..3
    const int cg = w & 3;           // channel group: 16 ch
    const int np = w >> 2;          // node panel: 64 nodes

    float acc[8][4];
#pragma unroll
    for (int i = 0; i < 8; i++)
#pragma unroll
        for (int j = 0; j < 4; j++) acc[i][j] = 0.f;

    const float* wh = g_wsh + (size_t)(h * FO + cg * 16) * FIN;
    const float* wl = g_wsl + (size_t)(h * FO + cg * 16) * FIN;

    for (int kc = 0; kc < 4; kc++) {
        __syncthreads();
#pragma unroll
        for (int i = 0; i < 4; i++) {
            int slot = tid + i * 256;          // 0..1023
            int row = slot >> 3;
            int c4 = (slot & 7) * 4;
            size_t gi = (size_t)(nBase + row) * 512 + h * 128 + kc * 32 + c4;
            float4 v = *(const float4*)(g_z + gi);
            float4 hi4, lo4;
            hi4.x = tf32_rna(v.x); lo4.x = tf32_rna(v.x - hi4.x);
            hi4.y = tf32_rna(v.y); lo4.y = tf32_rna(v.y - hi4.y);
            hi4.z = tf32_rna(v.z); lo4.z = tf32_rna(v.z - hi4.z);
            hi4.w = tf32_rna(v.w); lo4.w = tf32_rna(v.w - hi4.w);
            *(float4*)(&zsh[row][c4]) = hi4;
            *(float4*)(&zsl[row][c4]) = lo4;
        }
        __syncthreads();

#pragma unroll
        for (int kf = 0; kf < 4; kf++) {
            const int k0 = kc * 32 + kf * 8;
            uint32_t ah0 = __float_as_uint(__ldg(wh + (g)     * FIN + k0 + t4));
            uint32_t ah1 = __float_as_uint(__ldg(wh + (g + 8) * FIN + k0 + t4));
            uint32_t ah2 = __float_as_uint(__ldg(wh + (g)     * FIN + k0 + t4 + 4));
            uint32_t ah3 = __float_as_uint(__ldg(wh + (g + 8) * FIN + k0 + t4 + 4));
            uint32_t al0 = __float_as_uint(__ldg(wl + (g)     * FIN + k0 + t4));
            uint32_t al1 = __float_as_uint(__ldg(wl + (g + 8) * FIN + k0 + t4));
            uint32_t al2 = __float_as_uint(__ldg(wl + (g)     * FIN + k0 + t4 + 4));
            uint32_t al3 = __float_as_uint(__ldg(wl + (g + 8) * FIN + k0 + t4 + 4));
            const int ks = kf * 8;
#pragma unroll
            for (int nf = 0; nf < 8; nf++) {
                int row = np * 64 + nf * 8 + g;
                uint32_t bh0 = __float_as_uint(zsh[row][ks + t4]);
                uint32_t bh1 = __float_as_uint(zsh[row][ks + t4 + 4]);
                uint32_t bl0 = __float_as_uint(zsl[row][ks + t4]);
                uint32_t bl1 = __float_as_uint(zsl[row][ks + t4 + 4]);
                mma_tf32(acc[nf][0], acc[nf][1], acc[nf][2], acc[nf][3],
                         ah0, ah1, ah2, ah3, bh0, bh1);
                mma_tf32(acc[nf][0], acc[nf][1], acc[nf][2], acc[nf][3],
                         ah0, ah1, ah2, ah3, bl0, bl1);
                mma_tf32(acc[nf][0], acc[nf][1], acc[nf][2], acc[nf][3],
                         al0, al1, al2, al3, bh0, bh1);
            }
        }
    }

    int ch  = h * FO + cg * 16 + g;
    int ch8 = ch + 8;
    float bg  = __ldg(bias + ch);
    float bg8 = __ldg(bias + ch8);
#pragma unroll
    for (int nf = 0; nf < 8; nf++) {
        int n0 = nBase + np * 64 + nf * 8 + 2 * t4;
        int n1 = n0 + 1;
        if (n0 < NN) {
            out[(size_t)n0 * NOUT + ch]  = acc[nf][0] + bg;
            out[(size_t)n0 * NOUT + ch8] = acc[nf][2] + bg8;
        }
        if (n1 < NN) {
            out[(size_t)n1 * NOUT + ch]  = acc[nf][1] + bg;
            out[(size_t)n1 * NOUT + ch8] = acc[nf][3] + bg8;
        }
    }
}

// ---------------- launch ----------------
extern "C" void kernel_launch(void* const* d_in, const int* in_sizes, int n_in,
                              void* d_out, int out_size) {
    const float* feat  = (const float*)d_in[0];
    const int*   src   = (const int*)d_in[1];
    const int*   dst   = (const int*)d_in[2];
    const float* fc_w  = (const float*)d_in[3];
    const float* al    = (const float*)d_in[4];
    const float* ar    = (const float*)d_in[5];
    const float* al1   = (const float*)d_in[6];
    const float* ar1   = (const float*)d_in[7];
    const float* bias  = (const float*)d_in[8];
    float* out = (float*)d_out;

    const int nch = (NN + 1023) / 1024;  // 49

    k_prep<<<PREPN / 256, 256>>>(al, ar, al1, ar1, fc_w);   // covers NN and NOUT*FIN
    k_hist<<<(EE / 4 + 255) / 256, 256>>>(dst);
    k_node<<<(NN * 32 + 255) / 256, 256>>>(feat, al1, ar1);
    k_scan1<<<nch, 1024>>>();
    k_scan2<<<1, 32>>>(nch);
    k_scan3<<<nch, 1024>>>();
    k_scatter<<<(EE / 4 + 255) / 256, 256>>>(src, dst);
    k_agg<<<(NN * 32 + 255) / 256, 256>>>(feat);
    k_tc<<<dim3(HH, NR / 128), 256>>>(bias, out);
}